// round 5
// baseline (speedup 1.0000x reference)
#include <cuda_runtime.h>
#include <cuda_bf16.h>
#include <math_constants.h>

// GeomAttention: B=2, L=S=2048, H=8, E=D=32, fp32.
// scores = (0.5*dot - 0.5*relu(qn2*kn2 - dot^2))/sqrt(E); softmax; out = attn @ V.
//
// R5: NO online softmax. A pre-kernel computes KMIN(b,h)=min|k|^2; each row uses
// the fixed safe shift C = min(scale*qn2*KMIN, 70) so exp(score + C) neither
// overflows nor fully underflows (ratios identical to reference). Straight-line
// inner loop, ~110 regs -> all 1024 blocks resident in one wave (SPLITS=4).
// 2 query rows per thread, packed fma.rn.f32x2, fused last-block merge.

static constexpr int B_ = 2, L_ = 2048, H_ = 8, E_ = 32;
static constexpr int SPLITS = 4;
static constexpr int SKEYS  = L_ / SPLITS;   // 512
static constexpr int TS = 64;                // keys per SMEM tile
static constexpr int THREADS = 64;           // 2 warps
static constexpr int ROWSPB = 2 * THREADS;   // 128 rows per block
static constexpr int NR = B_ * L_ * H_;      // 32768 rows
static constexpr int NGROUPS = (L_ / ROWSPB) * H_ * B_;  // 256

__device__ float  g_l[SPLITS * NR];
__device__ float4 g_acc[SPLITS * NR * 8];
__device__ float  g_kmin[B_ * H_];
__device__ int    g_cnt[NGROUPS];            // zero-init; self-resetting

typedef unsigned long long u64;

__device__ __forceinline__ u64 pk2(float a, float b) {
    u64 r; asm("mov.b64 %0, {%1,%2};" : "=l"(r) : "f"(a), "f"(b)); return r;
}
__device__ __forceinline__ float2 upk2(u64 v) {
    float2 r; asm("mov.b64 {%0,%1}, %2;" : "=f"(r.x), "=f"(r.y) : "l"(v)); return r;
}
__device__ __forceinline__ u64 ffma2(u64 a, u64 b, u64 c) {
    u64 d; asm("fma.rn.f32x2 %0, %1, %2, %3;" : "=l"(d) : "l"(a), "l"(b), "l"(c)); return d;
}

// ---- pre-kernel: per-(b,h) minimum key squared-norm ----
__global__ __launch_bounds__(256) void kmin_kernel(const float* __restrict__ K)
{
    const int bh = blockIdx.x;               // 0..B*H-1
    const int b = bh / H_, h = bh % H_;
    const float* kbase = K + (((size_t)b * L_) * H_ + h) * E_;
    float mn = CUDART_INF_F;
    for (int s = threadIdx.x; s < L_; s += 256) {
        const float4* kp = (const float4*)(kbase + (size_t)s * (H_ * E_));
        float kn = 0.f;
        #pragma unroll
        for (int j = 0; j < 8; j++) {
            float4 v = kp[j];
            kn += v.x*v.x + v.y*v.y + v.z*v.z + v.w*v.w;
        }
        mn = fminf(mn, kn);
    }
    #pragma unroll
    for (int o = 16; o; o >>= 1) mn = fminf(mn, __shfl_xor_sync(0xffffffffu, mn, o));
    __shared__ float red[8];
    if ((threadIdx.x & 31) == 0) red[threadIdx.x >> 5] = mn;
    __syncthreads();
    if (threadIdx.x == 0) {
        float r = red[0];
        #pragma unroll
        for (int w = 1; w < 8; w++) r = fminf(r, red[w]);
        g_kmin[bh] = r;
    }
}

__global__ __launch_bounds__(THREADS, 8) void geom_attn_fused(
    const float* __restrict__ Q, const float* __restrict__ K,
    const float* __restrict__ V, float* __restrict__ O)
{
    __shared__ float4 sK[TS * 8];
    __shared__ float4 sV[TS * 8];
    __shared__ float  sKn2[TS];
    __shared__ int    sLast;

    const int tid   = threadIdx.x;
    const int h     = blockIdx.y;
    const int bz    = blockIdx.z;
    const int b     = bz >> 2;                 // SPLITS == 4
    const int split = bz & 3;
    const int lbase = blockIdx.x * ROWSPB;
    const int l0    = lbase + tid;
    const int l1    = l0 + THREADS;

    // ---- load 2 query rows; |q|^2 each ----
    const float* qp0 = Q + (((size_t)b * L_ + l0) * H_ + h) * E_;
    const float* qp1 = Q + (((size_t)b * L_ + l1) * H_ + h) * E_;
    u64 qa[16], qb[16];
    float qn2a = 0.f, qn2b = 0.f;
    #pragma unroll
    for (int j = 0; j < 8; j++) {
        float4 t = ((const float4*)qp0)[j];
        qa[2*j] = pk2(t.x, t.y); qa[2*j+1] = pk2(t.z, t.w);
        qn2a += t.x*t.x + t.y*t.y + t.z*t.z + t.w*t.w;
        float4 u = ((const float4*)qp1)[j];
        qb[2*j] = pk2(u.x, u.y); qb[2*j+1] = pk2(u.z, u.w);
        qn2b += u.x*u.x + u.y*u.y + u.z*u.z + u.w*u.w;
    }

    const float scale = 0.5f * rsqrtf((float)E_);
    const float kmin  = g_kmin[b * H_ + h];
    // Safe fixed shift: exp(score + C) in [~e^-large, ~e^78]; ratios unchanged.
    const float Ca = fminf(scale * qn2a * kmin, 70.f);
    const float Cb = fminf(scale * qn2b * kmin, 70.f);

    float ls0 = 0.f, ls1 = 0.f;
    u64 acca[16], accb[16];
    #pragma unroll
    for (int j = 0; j < 16; j++) { acca[j] = 0ull; accb[j] = 0ull; }

    const int key0 = split * SKEYS;
    const float* kbase = K + (((size_t)b * L_) * H_ + h) * E_;
    const float* vbase = V + (((size_t)b * L_) * H_ + h) * E_;

    for (int s0 = 0; s0 < SKEYS; s0 += TS) {
        #pragma unroll
        for (int i = tid; i < TS * 8; i += THREADS) {
            int r = i >> 3, j = i & 7;
            size_t off = (size_t)(key0 + s0 + r) * (H_ * E_);
            sK[i] = ((const float4*)(kbase + off))[j];
            sV[i] = ((const float4*)(vbase + off))[j];
        }
        __syncthreads();
        {   // per-key |k|^2 ; rotate j to avoid bank conflicts
            float kn = 0.f;
            #pragma unroll
            for (int jj = 0; jj < 8; jj++) {
                int j = (jj + tid) & 7;
                float4 kk = sK[tid * 8 + j];
                kn += kk.x*kk.x + kk.y*kk.y + kk.z*kk.z + kk.w*kk.w;
            }
            sKn2[tid] = kn;
        }
        __syncthreads();

        #pragma unroll 4
        for (int s = 0; s < TS; s++) {
            const ulonglong2* kp = (const ulonglong2*)&sK[s * 8];
            u64 a0 = 0ull, a1 = 0ull, b0 = 0ull, b1 = 0ull;
            #pragma unroll
            for (int j = 0; j < 8; j++) {
                ulonglong2 kk = kp[j];              // broadcast across warp
                a0 = ffma2(qa[2*j],   kk.x, a0);
                a1 = ffma2(qa[2*j+1], kk.y, a1);
                b0 = ffma2(qb[2*j],   kk.x, b0);
                b1 = ffma2(qb[2*j+1], kk.y, b1);
            }
            float2 ra0 = upk2(a0), ra1 = upk2(a1);
            float2 rb0 = upk2(b0), rb1 = upk2(b1);
            float dota = (ra0.x + ra0.y) + (ra1.x + ra1.y);
            float dotb = (rb0.x + rb0.y) + (rb1.x + rb1.y);
            float kn2  = sKn2[s];
            float wa = fmaxf(fmaf(qn2a, kn2, -dota * dota), 0.f);
            float wb = fmaxf(fmaf(qn2b, kn2, -dotb * dotb), 0.f);
            float pa = __expf(fmaf(scale, dota - wa, Ca));
            float pb = __expf(fmaf(scale, dotb - wb, Cb));
            ls0 += pa; ls1 += pb;

            u64 ppa = pk2(pa, pa), ppb = pk2(pb, pb);
            const ulonglong2* vp = (const ulonglong2*)&sV[s * 8];
            #pragma unroll
            for (int j = 0; j < 8; j++) {
                ulonglong2 vv = vp[j];
                acca[2*j]   = ffma2(ppa, vv.x, acca[2*j]);
                acca[2*j+1] = ffma2(ppa, vv.y, acca[2*j+1]);
                accb[2*j]   = ffma2(ppb, vv.x, accb[2*j]);
                accb[2*j+1] = ffma2(ppb, vv.y, accb[2*j+1]);
            }
        }
        __syncthreads();
    }

    // ---- write partials ----
    const int r0 = ((b * L_ + l0) * H_ + h);
    const int r1 = ((b * L_ + l1) * H_ + h);
    g_l[split * NR + r0] = ls0;
    g_l[split * NR + r1] = ls1;
    float4* pa4 = &g_acc[(size_t)(split * NR + r0) * 8];
    float4* pb4 = &g_acc[(size_t)(split * NR + r1) * 8];
    #pragma unroll
    for (int j = 0; j < 8; j++) {
        float2 x = upk2(acca[2*j]), y = upk2(acca[2*j+1]);
        pa4[j] = make_float4(x.x, x.y, y.x, y.y);
        float2 u = upk2(accb[2*j]), v = upk2(accb[2*j+1]);
        pb4[j] = make_float4(u.x, u.y, v.x, v.y);
    }

    // ---- last block of this group merges the splits (plain sums) ----
    const int g = blockIdx.x + (L_ / ROWSPB) * (h + H_ * b);
    __threadfence();
    if (tid == 0) {
        int prev = atomicAdd(&g_cnt[g], 1);
        sLast = (prev == SPLITS - 1);
    }
    __syncthreads();
    if (!sLast) return;
    __threadfence();

    // 64 threads merge 128 rows x 8 float4 chunks = 1024 items.
    #pragma unroll 1
    for (int it = 0; it < (ROWSPB * 8) / THREADS; it++) {
        int item = it * THREADS + tid;
        int rl = item >> 3;
        int jj = item & 7;
        int r  = ((b * L_ + lbase + rl) * H_ + h);
        float denom = 0.f;
        float4 o = make_float4(0.f, 0.f, 0.f, 0.f);
        #pragma unroll
        for (int sp = 0; sp < SPLITS; sp++) {
            denom += g_l[sp * NR + r];
            float4 a = g_acc[(size_t)(sp * NR + r) * 8 + jj];
            o.x += a.x; o.y += a.y; o.z += a.z; o.w += a.w;
        }
        float inv = 1.0f / denom;
        o.x *= inv; o.y *= inv; o.z *= inv; o.w *= inv;
        ((float4*)O)[(size_t)r * 8 + jj] = o;
    }
    if (tid == 0) g_cnt[g] = 0;   // self-reset for next graph replay
}

extern "C" void kernel_launch(void* const* d_in, const int* in_sizes, int n_in,
                              void* d_out, int out_size) {
    const float* Q = (const float*)d_in[0];
    const float* K = (const float*)d_in[1];
    const float* V = (const float*)d_in[2];
    float* O = (float*)d_out;
    (void)in_sizes; (void)n_in; (void)out_size;
    kmin_kernel<<<B_ * H_, 256>>>(K);
    dim3 grid(L_ / ROWSPB, H_, B_ * SPLITS);   // 16 x 8 x 8 = 1024 blocks
    geom_attn_fused<<<grid, THREADS>>>(Q, K, V, O);
}

// round 6
// speedup vs baseline: 2.0144x; 2.0144x over previous
#include <cuda_runtime.h>
#include <cuda_bf16.h>
#include <math_constants.h>

// GeomAttention: B=2, L=S=2048, H=8, E=D=32, fp32.
// scores = (0.5*dot - 0.5*relu(qn2*kn2 - dot^2))/sqrt(E); softmax; out = attn @ V.
//
// R6: R5's shift-softmax (no online rescale; pre-kernel KMIN gives a provably
// safe fixed shift per row) but WITHOUT the register cap that caused R5's
// spill (launch_bounds(64,5) -> ~190 regs, no LDL/STL), and SPLITS=2 so all
// 512 blocks are resident in a single wave. 2 query rows/thread, packed
// fma.rn.f32x2, fused last-block merge.

static constexpr int B_ = 2, L_ = 2048, H_ = 8, E_ = 32;
static constexpr int SPLITS = 2;
static constexpr int SKEYS  = L_ / SPLITS;   // 1024
static constexpr int TS = 64;                // keys per SMEM tile
static constexpr int THREADS = 64;           // 2 warps
static constexpr int ROWSPB = 2 * THREADS;   // 128 rows per block
static constexpr int NR = B_ * L_ * H_;      // 32768 rows
static constexpr int NGROUPS = (L_ / ROWSPB) * H_ * B_;  // 256

__device__ float  g_l[SPLITS * NR];
__device__ float4 g_acc[SPLITS * NR * 8];
__device__ float  g_kmin[B_ * H_];
__device__ int    g_cnt[NGROUPS];            // zero-init; self-resetting

typedef unsigned long long u64;

__device__ __forceinline__ u64 pk2(float a, float b) {
    u64 r; asm("mov.b64 %0, {%1,%2};" : "=l"(r) : "f"(a), "f"(b)); return r;
}
__device__ __forceinline__ float2 upk2(u64 v) {
    float2 r; asm("mov.b64 {%0,%1}, %2;" : "=f"(r.x), "=f"(r.y) : "l"(v)); return r;
}
__device__ __forceinline__ u64 ffma2(u64 a, u64 b, u64 c) {
    u64 d; asm("fma.rn.f32x2 %0, %1, %2, %3;" : "=l"(d) : "l"(a), "l"(b), "l"(c)); return d;
}

// ---- pre-kernel: per-(b,h) minimum key squared-norm ----
__global__ __launch_bounds__(256) void kmin_kernel(const float* __restrict__ K)
{
    const int bh = blockIdx.x;               // 0..B*H-1
    const int b = bh / H_, h = bh % H_;
    const float* kbase = K + (((size_t)b * L_) * H_ + h) * E_;
    float mn = CUDART_INF_F;
    for (int s = threadIdx.x; s < L_; s += 256) {
        const float4* kp = (const float4*)(kbase + (size_t)s * (H_ * E_));
        float kn = 0.f;
        #pragma unroll
        for (int j = 0; j < 8; j++) {
            float4 v = kp[j];
            kn += v.x*v.x + v.y*v.y + v.z*v.z + v.w*v.w;
        }
        mn = fminf(mn, kn);
    }
    #pragma unroll
    for (int o = 16; o; o >>= 1) mn = fminf(mn, __shfl_xor_sync(0xffffffffu, mn, o));
    __shared__ float red[8];
    if ((threadIdx.x & 31) == 0) red[threadIdx.x >> 5] = mn;
    __syncthreads();
    if (threadIdx.x == 0) {
        float r = red[0];
        #pragma unroll
        for (int w = 1; w < 8; w++) r = fminf(r, red[w]);
        g_kmin[bh] = r;
    }
}

__global__ __launch_bounds__(THREADS, 5) void geom_attn_fused(
    const float* __restrict__ Q, const float* __restrict__ K,
    const float* __restrict__ V, float* __restrict__ O)
{
    __shared__ float4 sK[TS * 8];
    __shared__ float4 sV[TS * 8];
    __shared__ float  sKn2[TS];
    __shared__ int    sLast;

    const int tid   = threadIdx.x;
    const int h     = blockIdx.y;
    const int bz    = blockIdx.z;
    const int b     = bz >> 1;                 // SPLITS == 2
    const int split = bz & 1;
    const int lbase = blockIdx.x * ROWSPB;
    const int l0    = lbase + tid;
    const int l1    = l0 + THREADS;

    // ---- load 2 query rows; |q|^2 each ----
    const float* qp0 = Q + (((size_t)b * L_ + l0) * H_ + h) * E_;
    const float* qp1 = Q + (((size_t)b * L_ + l1) * H_ + h) * E_;
    u64 qa[16], qb[16];
    float qn2a = 0.f, qn2b = 0.f;
    #pragma unroll
    for (int j = 0; j < 8; j++) {
        float4 t = ((const float4*)qp0)[j];
        qa[2*j] = pk2(t.x, t.y); qa[2*j+1] = pk2(t.z, t.w);
        qn2a += t.x*t.x + t.y*t.y + t.z*t.z + t.w*t.w;
        float4 u = ((const float4*)qp1)[j];
        qb[2*j] = pk2(u.x, u.y); qb[2*j+1] = pk2(u.z, u.w);
        qn2b += u.x*u.x + u.y*u.y + u.z*u.z + u.w*u.w;
    }

    const float scale = 0.5f * rsqrtf((float)E_);
    const float kmin  = g_kmin[b * H_ + h];
    // Safe fixed shift: exp(score + C) neither overflows nor all-underflows.
    const float Ca = fminf(scale * qn2a * kmin, 70.f);
    const float Cb = fminf(scale * qn2b * kmin, 70.f);

    float ls0 = 0.f, ls1 = 0.f;
    u64 acca[16], accb[16];
    #pragma unroll
    for (int j = 0; j < 16; j++) { acca[j] = 0ull; accb[j] = 0ull; }

    const int key0 = split * SKEYS;
    const float* kbase = K + (((size_t)b * L_) * H_ + h) * E_;
    const float* vbase = V + (((size_t)b * L_) * H_ + h) * E_;

    for (int s0 = 0; s0 < SKEYS; s0 += TS) {
        #pragma unroll
        for (int i = tid; i < TS * 8; i += THREADS) {
            int r = i >> 3, j = i & 7;
            size_t off = (size_t)(key0 + s0 + r) * (H_ * E_);
            sK[i] = ((const float4*)(kbase + off))[j];
            sV[i] = ((const float4*)(vbase + off))[j];
        }
        __syncthreads();
        {   // per-key |k|^2 ; rotate j to avoid bank conflicts
            float kn = 0.f;
            #pragma unroll
            for (int jj = 0; jj < 8; jj++) {
                int j = (jj + tid) & 7;
                float4 kk = sK[tid * 8 + j];
                kn += kk.x*kk.x + kk.y*kk.y + kk.z*kk.z + kk.w*kk.w;
            }
            sKn2[tid] = kn;
        }
        __syncthreads();

        #pragma unroll 4
        for (int s = 0; s < TS; s++) {
            const ulonglong2* kp = (const ulonglong2*)&sK[s * 8];
            u64 a0 = 0ull, a1 = 0ull, b0 = 0ull, b1 = 0ull;
            #pragma unroll
            for (int j = 0; j < 8; j++) {
                ulonglong2 kk = kp[j];              // broadcast across warp
                a0 = ffma2(qa[2*j],   kk.x, a0);
                a1 = ffma2(qa[2*j+1], kk.y, a1);
                b0 = ffma2(qb[2*j],   kk.x, b0);
                b1 = ffma2(qb[2*j+1], kk.y, b1);
            }
            float2 ra0 = upk2(a0), ra1 = upk2(a1);
            float2 rb0 = upk2(b0), rb1 = upk2(b1);
            float dota = (ra0.x + ra0.y) + (ra1.x + ra1.y);
            float dotb = (rb0.x + rb0.y) + (rb1.x + rb1.y);
            float kn2  = sKn2[s];
            float wa = fmaxf(fmaf(qn2a, kn2, -dota * dota), 0.f);
            float wb = fmaxf(fmaf(qn2b, kn2, -dotb * dotb), 0.f);
            float pa = __expf(fmaf(scale, dota - wa, Ca));
            float pb = __expf(fmaf(scale, dotb - wb, Cb));
            ls0 += pa; ls1 += pb;

            u64 ppa = pk2(pa, pa), ppb = pk2(pb, pb);
            const ulonglong2* vp = (const ulonglong2*)&sV[s * 8];
            #pragma unroll
            for (int j = 0; j < 8; j++) {
                ulonglong2 vv = vp[j];
                acca[2*j]   = ffma2(ppa, vv.x, acca[2*j]);
                acca[2*j+1] = ffma2(ppa, vv.y, acca[2*j+1]);
                accb[2*j]   = ffma2(ppb, vv.x, accb[2*j]);
                accb[2*j+1] = ffma2(ppb, vv.y, accb[2*j+1]);
            }
        }
        __syncthreads();
    }

    // ---- write partials ----
    const int r0 = ((b * L_ + l0) * H_ + h);
    const int r1 = ((b * L_ + l1) * H_ + h);
    g_l[split * NR + r0] = ls0;
    g_l[split * NR + r1] = ls1;
    float4* pa4 = &g_acc[(size_t)(split * NR + r0) * 8];
    float4* pb4 = &g_acc[(size_t)(split * NR + r1) * 8];
    #pragma unroll
    for (int j = 0; j < 8; j++) {
        float2 x = upk2(acca[2*j]), y = upk2(acca[2*j+1]);
        pa4[j] = make_float4(x.x, x.y, y.x, y.y);
        float2 u = upk2(accb[2*j]), v = upk2(accb[2*j+1]);
        pb4[j] = make_float4(u.x, u.y, v.x, v.y);
    }

    // ---- last block of this group merges the splits (plain sums) ----
    const int g = blockIdx.x + (L_ / ROWSPB) * (h + H_ * b);
    __threadfence();
    if (tid == 0) {
        int prev = atomicAdd(&g_cnt[g], 1);
        sLast = (prev == SPLITS - 1);
    }
    __syncthreads();
    if (!sLast) return;
    __threadfence();

    // 64 threads merge 128 rows x 8 float4 chunks = 1024 items.
    #pragma unroll 1
    for (int it = 0; it < (ROWSPB * 8) / THREADS; it++) {
        int item = it * THREADS + tid;
        int rl = item >> 3;
        int jj = item & 7;
        int r  = ((b * L_ + lbase + rl) * H_ + h);
        float denom = 0.f;
        float4 o = make_float4(0.f, 0.f, 0.f, 0.f);
        #pragma unroll
        for (int sp = 0; sp < SPLITS; sp++) {
            denom += g_l[sp * NR + r];
            float4 a = g_acc[(size_t)(sp * NR + r) * 8 + jj];
            o.x += a.x; o.y += a.y; o.z += a.z; o.w += a.w;
        }
        float inv = 1.0f / denom;
        o.x *= inv; o.y *= inv; o.z *= inv; o.w *= inv;
        ((float4*)O)[(size_t)r * 8 + jj] = o;
    }
    if (tid == 0) g_cnt[g] = 0;   // self-reset for next graph replay
}

extern "C" void kernel_launch(void* const* d_in, const int* in_sizes, int n_in,
                              void* d_out, int out_size) {
    const float* Q = (const float*)d_in[0];
    const float* K = (const float*)d_in[1];
    const float* V = (const float*)d_in[2];
    float* O = (float*)d_out;
    (void)in_sizes; (void)n_in; (void)out_size;
    kmin_kernel<<<B_ * H_, 256>>>(K);
    dim3 grid(L_ / ROWSPB, H_, B_ * SPLITS);   // 16 x 8 x 4 = 512 blocks
    geom_attn_fused<<<grid, THREADS>>>(Q, K, V, O);
}

// round 7
// speedup vs baseline: 2.1925x; 1.0884x over previous
#include <cuda_runtime.h>
#include <cuda_bf16.h>
#include <math_constants.h>

// GeomAttention: B=2, L=S=2048, H=8, E=D=32, fp32.
// By Cauchy-Schwarz dot^2 <= qn2*kn2, so relu never fires:
//   score = c*(dot + dot^2) - c*qn2*kn2,  c = 0.5/sqrt(E).
// Shift softmax: C = min(c*qn2*KMIN, 70) is a safe fixed shift (no online max).
//
// R7: 1 query row per thread (regs ~105 -> 13.8 warps/SM resident, was 6.9),
// chunk-8 scoring for ILP (phase1 scores, phase2 exp+PV, both straight-line),
// SPLITS=2 fused with last-block merge, packed fma.rn.f32x2.

static constexpr int B_ = 2, L_ = 2048, H_ = 8, E_ = 32;
static constexpr int SPLITS = 2;
static constexpr int SKEYS  = L_ / SPLITS;   // 1024
static constexpr int TS = 64;                // keys per SMEM tile
static constexpr int CH = 8;                 // keys per score chunk
static constexpr int THREADS = 64;           // 2 warps
static constexpr int ROWSPB = THREADS;       // 64 rows per block (1/thread)
static constexpr int NR = B_ * L_ * H_;      // 32768 rows
static constexpr int NGROUPS = (L_ / ROWSPB) * H_ * B_;  // 512

__device__ float  g_l[SPLITS * NR];
__device__ float4 g_acc[SPLITS * NR * 8];
__device__ float  g_kmin[B_ * H_];
__device__ int    g_cnt[NGROUPS];            // zero-init; self-resetting

typedef unsigned long long u64;

__device__ __forceinline__ u64 pk2(float a, float b) {
    u64 r; asm("mov.b64 %0, {%1,%2};" : "=l"(r) : "f"(a), "f"(b)); return r;
}
__device__ __forceinline__ float2 upk2(u64 v) {
    float2 r; asm("mov.b64 {%0,%1}, %2;" : "=f"(r.x), "=f"(r.y) : "l"(v)); return r;
}
__device__ __forceinline__ u64 ffma2(u64 a, u64 b, u64 c) {
    u64 d; asm("fma.rn.f32x2 %0, %1, %2, %3;" : "=l"(d) : "l"(a), "l"(b), "l"(c)); return d;
}

// ---- pre-kernel: per-(b,h) minimum key squared-norm ----
__global__ __launch_bounds__(256) void kmin_kernel(const float* __restrict__ K)
{
    const int bh = blockIdx.x;               // 0..B*H-1
    const int b = bh / H_, h = bh % H_;
    const float* kbase = K + (((size_t)b * L_) * H_ + h) * E_;
    float mn = CUDART_INF_F;
    for (int s = threadIdx.x; s < L_; s += 256) {
        const float4* kp = (const float4*)(kbase + (size_t)s * (H_ * E_));
        float kn = 0.f;
        #pragma unroll
        for (int j = 0; j < 8; j++) {
            float4 v = kp[j];
            kn += v.x*v.x + v.y*v.y + v.z*v.z + v.w*v.w;
        }
        mn = fminf(mn, kn);
    }
    #pragma unroll
    for (int o = 16; o; o >>= 1) mn = fminf(mn, __shfl_xor_sync(0xffffffffu, mn, o));
    __shared__ float red[8];
    if ((threadIdx.x & 31) == 0) red[threadIdx.x >> 5] = mn;
    __syncthreads();
    if (threadIdx.x == 0) {
        float r = red[0];
        #pragma unroll
        for (int w = 1; w < 8; w++) r = fminf(r, red[w]);
        g_kmin[bh] = r;
    }
}

__global__ __launch_bounds__(THREADS, 7) void geom_attn_fused(
    const float* __restrict__ Q, const float* __restrict__ K,
    const float* __restrict__ V, float* __restrict__ O)
{
    __shared__ float4 sK[TS * 8];
    __shared__ float4 sV[TS * 8];
    __shared__ float  sKn2[TS];
    __shared__ int    sLast;

    const int tid   = threadIdx.x;
    const int h     = blockIdx.y;
    const int bz    = blockIdx.z;
    const int b     = bz >> 1;                 // SPLITS == 2
    const int split = bz & 1;
    const int lbase = blockIdx.x * ROWSPB;
    const int l     = lbase + tid;

    // ---- load query row; |q|^2 ----
    const float* qp = Q + (((size_t)b * L_ + l) * H_ + h) * E_;
    u64 q[16];
    float qn2 = 0.f;
    #pragma unroll
    for (int j = 0; j < 8; j++) {
        float4 t = ((const float4*)qp)[j];
        q[2*j] = pk2(t.x, t.y); q[2*j+1] = pk2(t.z, t.w);
        qn2 += t.x*t.x + t.y*t.y + t.z*t.z + t.w*t.w;
    }

    const float c  = 0.5f * rsqrtf((float)E_);
    const float cq = c * qn2;
    const float C  = fminf(cq * g_kmin[b * H_ + h], 70.f);  // safe fixed shift

    float ls = 0.f;
    u64 acc[16];
    #pragma unroll
    for (int j = 0; j < 16; j++) acc[j] = 0ull;

    const int key0 = split * SKEYS;
    const float* kbase = K + (((size_t)b * L_) * H_ + h) * E_;
    const float* vbase = V + (((size_t)b * L_) * H_ + h) * E_;

    for (int s0 = 0; s0 < SKEYS; s0 += TS) {
        #pragma unroll
        for (int i = tid; i < TS * 8; i += THREADS) {
            int r = i >> 3, j = i & 7;
            size_t off = (size_t)(key0 + s0 + r) * (H_ * E_);
            sK[i] = ((const float4*)(kbase + off))[j];
            sV[i] = ((const float4*)(vbase + off))[j];
        }
        __syncthreads();
        {   // per-key |k|^2 ; rotate j to avoid bank conflicts
            float kn = 0.f;
            #pragma unroll
            for (int jj = 0; jj < 8; jj++) {
                int j = (jj + tid) & 7;
                float4 kk = sK[tid * 8 + j];
                kn += kk.x*kk.x + kk.y*kk.y + kk.z*kk.z + kk.w*kk.w;
            }
            sKn2[tid] = kn;
        }
        __syncthreads();

        for (int c0 = 0; c0 < TS; c0 += CH) {
            float sa[CH];
            // ---- phase 1: scores for CH keys (high ILP) ----
            #pragma unroll
            for (int u = 0; u < CH; u++) {
                const ulonglong2* kp = (const ulonglong2*)&sK[(c0 + u) * 8];
                u64 a0 = 0ull, a1 = 0ull;
                #pragma unroll
                for (int j = 0; j < 8; j++) {
                    ulonglong2 kk = kp[j];          // broadcast across warp
                    a0 = ffma2(q[2*j],   kk.x, a0);
                    a1 = ffma2(q[2*j+1], kk.y, a1);
                }
                float2 ra = upk2(a0), rb = upk2(a1);
                float dot = (ra.x + ra.y) + (rb.x + rb.y);
                float t = fmaf(dot, dot, dot);      // dot + dot^2
                sa[u] = fmaf(c, t, fmaf(-cq, sKn2[c0 + u], C));
            }
            // ---- phase 2: exp + PV accumulate (straight-line) ----
            #pragma unroll
            for (int u = 0; u < CH; u++) {
                float p = __expf(sa[u]);
                ls += p;
                u64 pp = pk2(p, p);
                const ulonglong2* vp = (const ulonglong2*)&sV[(c0 + u) * 8];
                #pragma unroll
                for (int j = 0; j < 8; j++) {
                    ulonglong2 vv = vp[j];
                    acc[2*j]   = ffma2(pp, vv.x, acc[2*j]);
                    acc[2*j+1] = ffma2(pp, vv.y, acc[2*j+1]);
                }
            }
        }
        __syncthreads();
    }

    // ---- write partials ----
    const int r0 = ((b * L_ + l) * H_ + h);
    g_l[split * NR + r0] = ls;
    float4* pa4 = &g_acc[(size_t)(split * NR + r0) * 8];
    #pragma unroll
    for (int j = 0; j < 8; j++) {
        float2 x = upk2(acc[2*j]), y = upk2(acc[2*j+1]);
        pa4[j] = make_float4(x.x, x.y, y.x, y.y);
    }

    // ---- last block of this group merges the splits (plain sums) ----
    const int g = blockIdx.x + (L_ / ROWSPB) * (h + H_ * b);
    __threadfence();
    if (tid == 0) {
        int prev = atomicAdd(&g_cnt[g], 1);
        sLast = (prev == SPLITS - 1);
    }
    __syncthreads();
    if (!sLast) return;
    __threadfence();

    // 64 threads merge 64 rows x 8 float4 chunks = 512 items.
    #pragma unroll 1
    for (int it = 0; it < (ROWSPB * 8) / THREADS; it++) {
        int item = it * THREADS + tid;
        int rl = item >> 3;
        int jj = item & 7;
        int r  = ((b * L_ + lbase + rl) * H_ + h);
        float denom = 0.f;
        float4 o = make_float4(0.f, 0.f, 0.f, 0.f);
        #pragma unroll
        for (int sp = 0; sp < SPLITS; sp++) {
            denom += g_l[sp * NR + r];
            float4 a = g_acc[(size_t)(sp * NR + r) * 8 + jj];
            o.x += a.x; o.y += a.y; o.z += a.z; o.w += a.w;
        }
        float inv = 1.0f / denom;
        o.x *= inv; o.y *= inv; o.z *= inv; o.w *= inv;
        ((float4*)O)[(size_t)r * 8 + jj] = o;
    }
    if (tid == 0) g_cnt[g] = 0;   // self-reset for next graph replay
}

extern "C" void kernel_launch(void* const* d_in, const int* in_sizes, int n_in,
                              void* d_out, int out_size) {
    const float* Q = (const float*)d_in[0];
    const float* K = (const float*)d_in[1];
    const float* V = (const float*)d_in[2];
    float* O = (float*)d_out;
    (void)in_sizes; (void)n_in; (void)out_size;
    kmin_kernel<<<B_ * H_, 256>>>(K);
    dim3 grid(L_ / ROWSPB, H_, B_ * SPLITS);   // 32 x 8 x 4 = 1024 blocks
    geom_attn_fused<<<grid, THREADS>>>(Q, K, V, O);
}